// round 1
// baseline (speedup 1.0000x reference)
#include <cuda_runtime.h>
#include <cstdint>

// Problem constants
#define B     4
#define C     128
#define H     64
#define W_    64
#define OUTC  128
#define NPTS  9          // KS*KS
#define HW    4096       // H*W
#define KDIM  1152       // C*NPTS
#define NCOL  16384      // B*HW
#define HP    66         // H + 2*PAD
#define WP    66

// Scratch (allocation-free rule: __device__ globals)
__device__ float g_col[(size_t)KDIM * NCOL];          // 75.5 MB im2col buffer
__device__ int4  g_midx[B * NPTS * HW];               // 4 gather indices per (b,n,ij)
__device__ float4 g_mw[B * NPTS * HW];                // 4 bilinear weights per (b,n,ij)

// ---------------------------------------------------------------------------
// Kernel 0: per (b, n, ij) compute the 4 bilinear taps (indices + weights).
// Exactly mirrors the reference's mask/clip logic. Out-of-padded-interior taps
// get weight 0 (padded value is 0, so contribution vanishes).
// ---------------------------------------------------------------------------
__global__ void meta_kernel(const float* __restrict__ offset) {
    int t = blockIdx.x * blockDim.x + threadIdx.x;
    if (t >= B * NPTS * HW) return;
    int ij = t & (HW - 1);
    int bn = t >> 12;
    int n = bn % NPTS;
    int b = bn / NPTS;
    int i = ij >> 6;
    int j = ij & 63;

    float offx = offset[((b * 18) + 2 * n) * HW + ij];
    float offy = offset[((b * 18) + 2 * n + 1) * HW + ij];

    float px = (float)(i + 1) + (float)(n / 3 - 1) + offx;
    float py = (float)(j + 1) + (float)(n % 3 - 1) + offy;

    float fx = floorf(px), fy = floorf(py);
    float qltx = fminf(fmaxf(fx, 0.f), (float)(HP - 1));
    float qlty = fminf(fmaxf(fy, 0.f), (float)(WP - 1));
    float qrbx = fminf(fmaxf(fx + 1.f, 0.f), (float)(HP - 1));
    float qrby = fminf(fmaxf(fy + 1.f, 0.f), (float)(WP - 1));

    // mask: outside [PAD, Hp-1-PAD] -> snap to floor
    if (px < 1.f || px > (float)(HP - 2)) px = fx;
    if (py < 1.f || py > (float)(WP - 2)) py = fy;
    px = fminf(fmaxf(px, 0.f), (float)(HP - 1));
    py = fminf(fmaxf(py, 0.f), (float)(WP - 1));

    float glt = (1.f + (qltx - px)) * (1.f + (qlty - py));
    float grb = (1.f - (qrbx - px)) * (1.f - (qrby - py));
    float glb = (1.f + (qltx - px)) * (1.f - (qrby - py));
    float grt = (1.f - (qrbx - px)) * (1.f + (qlty - py));

    int ltx = (int)qltx, lty = (int)qlty, rbx = (int)qrbx, rby = (int)qrby;

    int4 id;
    float4 w = make_float4(glt, grb, glb, grt);
    // tap -> linear index into the UNPADDED x plane; padding rows/cols are zero
    // so we zero the weight instead.
    // lt = (ltx,lty), rb = (rbx,rby), lb = (ltx,rby), rt = (rbx,lty)
    {
        int qx = ltx, qy = lty;
        bool v = (qx >= 1 && qx <= H && qy >= 1 && qy <= W_);
        id.x = v ? ((qx - 1) << 6) + (qy - 1) : 0;
        if (!v) w.x = 0.f;
    }
    {
        int qx = rbx, qy = rby;
        bool v = (qx >= 1 && qx <= H && qy >= 1 && qy <= W_);
        id.y = v ? ((qx - 1) << 6) + (qy - 1) : 0;
        if (!v) w.y = 0.f;
    }
    {
        int qx = ltx, qy = rby;
        bool v = (qx >= 1 && qx <= H && qy >= 1 && qy <= W_);
        id.z = v ? ((qx - 1) << 6) + (qy - 1) : 0;
        if (!v) w.z = 0.f;
    }
    {
        int qx = rbx, qy = lty;
        bool v = (qx >= 1 && qx <= H && qy >= 1 && qy <= W_);
        id.w = v ? ((qx - 1) << 6) + (qy - 1) : 0;
        if (!v) w.w = 0.f;
    }
    g_midx[t] = id;
    g_mw[t] = w;
}

// ---------------------------------------------------------------------------
// Kernel 1: deformable im2col. grid = (HW/256, C, B), block = 256 threads
// over ij. col[(c*9+n)][b*HW + ij] = bilinear sample of x[b,c] at tap (b,n,ij).
// ---------------------------------------------------------------------------
__global__ void __launch_bounds__(256) im2col_kernel(const float* __restrict__ x) {
    int ij = blockIdx.x * blockDim.x + threadIdx.x;   // 0..4095
    int c = blockIdx.y;
    int b = blockIdx.z;
    const float* __restrict__ xpl = x + (size_t)((b << 7) + c) * HW;

#pragma unroll
    for (int n = 0; n < NPTS; n++) {
        int mi = ((b * NPTS + n) << 12) + ij;
        int4 id = g_midx[mi];
        float4 w = g_mw[mi];
        float v = w.x * __ldg(&xpl[id.x]) + w.y * __ldg(&xpl[id.y]) +
                  w.z * __ldg(&xpl[id.z]) + w.w * __ldg(&xpl[id.w]);
        g_col[((size_t)(c * NPTS + n) << 14) + (b << 12) + ij] = v;
    }
}

// ---------------------------------------------------------------------------
// Kernel 2: SGEMM  out[o][bij] = sum_k Wt[o][k] * col[k][bij]
// M=128 (one block row), N=16384, K=1152. BM=BN=128, BK=16, 256 threads,
// 8x8 per-thread tile.
// ---------------------------------------------------------------------------
#define BK 16
__global__ void __launch_bounds__(256) gemm_kernel(const float* __restrict__ Wt,
                                                   float* __restrict__ out) {
    __shared__ float As[BK][128];
    __shared__ float Bs[BK][128];

    int tid = threadIdx.x;
    int tx = tid & 15;       // 0..15 -> n dimension
    int ty = tid >> 4;       // 0..15 -> m dimension
    int bn = blockIdx.x * 128;

    float acc[8][8];
#pragma unroll
    for (int im = 0; im < 8; im++)
#pragma unroll
        for (int in = 0; in < 8; in++) acc[im][in] = 0.f;

    for (int k0 = 0; k0 < KDIM; k0 += BK) {
        // load A tile: weight rows are contiguous in k (stride KDIM)
        {
            int o = tid >> 1;
            int kq = (tid & 1) * 8;
            const float* src = Wt + (size_t)o * KDIM + k0 + kq;
            float4 a0 = *(const float4*)src;
            float4 a1 = *(const float4*)(src + 4);
            As[kq + 0][o] = a0.x; As[kq + 1][o] = a0.y;
            As[kq + 2][o] = a0.z; As[kq + 3][o] = a0.w;
            As[kq + 4][o] = a1.x; As[kq + 5][o] = a1.y;
            As[kq + 6][o] = a1.z; As[kq + 7][o] = a1.w;
        }
        // load B tile: col rows contiguous along n
        {
            int r = tid >> 4;     // 0..15
            int c4 = tid & 15;    // 16 threads * 8 floats = 128 cols
            const float* src = g_col + ((size_t)(k0 + r) << 14) + bn + c4 * 8;
            float4 b0 = *(const float4*)src;
            float4 b1 = *(const float4*)(src + 4);
            *(float4*)&Bs[r][c4 * 8] = b0;
            *(float4*)&Bs[r][c4 * 8 + 4] = b1;
        }
        __syncthreads();

#pragma unroll
        for (int kk = 0; kk < BK; kk++) {
            float a[8], bb[8];
            float4 a0 = *(float4*)&As[kk][ty * 8];
            float4 a1 = *(float4*)&As[kk][ty * 8 + 4];
            float4 b0 = *(float4*)&Bs[kk][tx * 8];
            float4 b1 = *(float4*)&Bs[kk][tx * 8 + 4];
            a[0]=a0.x; a[1]=a0.y; a[2]=a0.z; a[3]=a0.w;
            a[4]=a1.x; a[5]=a1.y; a[6]=a1.z; a[7]=a1.w;
            bb[0]=b0.x; bb[1]=b0.y; bb[2]=b0.z; bb[3]=b0.w;
            bb[4]=b1.x; bb[5]=b1.y; bb[6]=b1.z; bb[7]=b1.w;
#pragma unroll
            for (int im = 0; im < 8; im++)
#pragma unroll
                for (int in = 0; in < 8; in++)
                    acc[im][in] = fmaf(a[im], bb[in], acc[im][in]);
        }
        __syncthreads();
    }

    // epilogue: column n_global = b*HW + ij ; out[(b*OUTC + m)*HW + ij]
#pragma unroll
    for (int im = 0; im < 8; im++) {
        int m = ty * 8 + im;
#pragma unroll
        for (int in = 0; in < 8; in++) {
            int ng = bn + tx * 8 + in;
            int b = ng >> 12;
            int ij = ng & (HW - 1);
            out[(size_t)(((b << 7) + m) << 12) + ij] = acc[im][in];
        }
    }
}

// ---------------------------------------------------------------------------
extern "C" void kernel_launch(void* const* d_in, const int* in_sizes, int n_in,
                              void* d_out, int out_size) {
    const float* x      = (const float*)d_in[0];   // (4,128,64,64)
    const float* offset = (const float*)d_in[1];   // (4,18,64,64)
    const float* weight = (const float*)d_in[2];   // (128,128,3,3)
    float* out = (float*)d_out;                    // (4,128,64,64)

    (void)in_sizes; (void)n_in; (void)out_size;

    // Kernel 0: sampling metadata (147456 items)
    meta_kernel<<<(B * NPTS * HW + 255) / 256, 256>>>(offset);

    // Kernel 1: deformable im2col
    dim3 g1(HW / 256, C, B);
    im2col_kernel<<<g1, 256>>>(x);

    // Kernel 2: GEMM 128 x 16384 x 1152
    gemm_kernel<<<NCOL / 128, 256>>>(weight, out);
}

// round 2
// speedup vs baseline: 1.8716x; 1.8716x over previous
#include <cuda_runtime.h>
#include <cstdint>

// Problem constants
#define B     4
#define C     128
#define H     64
#define W_    64
#define OUTC  128
#define NPTS  9
#define HW    4096
#define KDIM  1152       // C*NPTS
#define NCOL  16384      // B*HW
#define HP    66
#define WP    66

// Scratch (allocation-free rule: __device__ globals)
__device__ float g_col[(size_t)KDIM * NCOL];          // 75.5 MB im2col buffer
__device__ int4  g_midx[B * NPTS * HW];
__device__ float4 g_mw[B * NPTS * HW];

__device__ __forceinline__ uint32_t f2tf32(float f) {
    uint32_t r;
    asm("cvt.rna.tf32.f32 %0, %1;" : "=r"(r) : "f"(f));
    return r;
}

// ---------------------------------------------------------------------------
// Kernel 0: sampling metadata (indices + bilinear weights), mirrors reference.
// ---------------------------------------------------------------------------
__global__ void meta_kernel(const float* __restrict__ offset) {
    int t = blockIdx.x * blockDim.x + threadIdx.x;
    if (t >= B * NPTS * HW) return;
    int ij = t & (HW - 1);
    int bn = t >> 12;
    int n = bn % NPTS;
    int b = bn / NPTS;
    int i = ij >> 6;
    int j = ij & 63;

    float offx = offset[((b * 18) + 2 * n) * HW + ij];
    float offy = offset[((b * 18) + 2 * n + 1) * HW + ij];

    float px = (float)(i + 1) + (float)(n / 3 - 1) + offx;
    float py = (float)(j + 1) + (float)(n % 3 - 1) + offy;

    float fx = floorf(px), fy = floorf(py);
    float qltx = fminf(fmaxf(fx, 0.f), (float)(HP - 1));
    float qlty = fminf(fmaxf(fy, 0.f), (float)(WP - 1));
    float qrbx = fminf(fmaxf(fx + 1.f, 0.f), (float)(HP - 1));
    float qrby = fminf(fmaxf(fy + 1.f, 0.f), (float)(WP - 1));

    if (px < 1.f || px > (float)(HP - 2)) px = fx;
    if (py < 1.f || py > (float)(WP - 2)) py = fy;
    px = fminf(fmaxf(px, 0.f), (float)(HP - 1));
    py = fminf(fmaxf(py, 0.f), (float)(WP - 1));

    float glt = (1.f + (qltx - px)) * (1.f + (qlty - py));
    float grb = (1.f - (qrbx - px)) * (1.f - (qrby - py));
    float glb = (1.f + (qltx - px)) * (1.f - (qrby - py));
    float grt = (1.f - (qrbx - px)) * (1.f + (qlty - py));

    int ltx = (int)qltx, lty = (int)qlty, rbx = (int)qrbx, rby = (int)qrby;

    int4 id;
    float4 w = make_float4(glt, grb, glb, grt);
    {
        int qx = ltx, qy = lty;
        bool v = (qx >= 1 && qx <= H && qy >= 1 && qy <= W_);
        id.x = v ? ((qx - 1) << 6) + (qy - 1) : 0;
        if (!v) w.x = 0.f;
    }
    {
        int qx = rbx, qy = rby;
        bool v = (qx >= 1 && qx <= H && qy >= 1 && qy <= W_);
        id.y = v ? ((qx - 1) << 6) + (qy - 1) : 0;
        if (!v) w.y = 0.f;
    }
    {
        int qx = ltx, qy = rby;
        bool v = (qx >= 1 && qx <= H && qy >= 1 && qy <= W_);
        id.z = v ? ((qx - 1) << 6) + (qy - 1) : 0;
        if (!v) w.z = 0.f;
    }
    {
        int qx = rbx, qy = lty;
        bool v = (qx >= 1 && qx <= H && qy >= 1 && qy <= W_);
        id.w = v ? ((qx - 1) << 6) + (qy - 1) : 0;
        if (!v) w.w = 0.f;
    }
    g_midx[t] = id;
    g_mw[t] = w;
}

// ---------------------------------------------------------------------------
// Kernel 1: deformable im2col, metadata hoisted out of the channel loop.
// grid = (HW/128, B, C/32), block = 128. Each thread: one ij, loops n outer
// (meta loaded once), 32 channels inner.
// ---------------------------------------------------------------------------
__global__ void __launch_bounds__(128) im2col_kernel(const float* __restrict__ x) {
    int ij = blockIdx.x * 128 + threadIdx.x;
    int b = blockIdx.y;
    int c0 = blockIdx.z * 32;
    const float* __restrict__ xb = x + ((size_t)(b << 7) + c0) * HW;

#pragma unroll
    for (int n = 0; n < NPTS; n++) {
        int mi = ((b * NPTS + n) << 12) + ij;
        int4 id = g_midx[mi];
        float4 w = g_mw[mi];
        const float* p = xb;
        float* dst = g_col + ((size_t)((c0)*NPTS + n) << 14) + (b << 12) + ij;
#pragma unroll 4
        for (int c = 0; c < 32; c++) {
            float v = w.x * __ldg(&p[id.x]) + w.y * __ldg(&p[id.y]) +
                      w.z * __ldg(&p[id.z]) + w.w * __ldg(&p[id.w]);
            *dst = v;
            p += HW;
            dst += (size_t)NPTS << 14;
        }
    }
}

// ---------------------------------------------------------------------------
// Kernel 2: TF32 tensor-core GEMM. out[128,16384] = W[128,1152] @ col[1152,16384]
// BM=128, BN=128, BK=16, 256 threads = 8 warps (2x4), warp tile 64x32,
// mma.sync.m16n8k8.tf32. Conflict-free SMEM layouts (pad 8, m-pair permute).
// ---------------------------------------------------------------------------
#define GBK 16
#define AROW 136   // 128 + 8 pad floats
#define BROW 136

__global__ void __launch_bounds__(256, 1) gemm_tc(const float* __restrict__ Wt,
                                                  float* __restrict__ out) {
    __shared__ float As[GBK][AROW];   // [k][perm(m)]
    __shared__ float Bs[GBK][BROW];   // [k][n]

    int tid = threadIdx.x;
    int warp = tid >> 5, lane = tid & 31;
    int q = lane & 3, g = lane >> 2;      // quad id / group id
    int wm = warp >> 2, wn = warp & 3;    // warp grid 2(m) x 4(n)
    int bn = blockIdx.x * 128;

    float acc[4][4][4];
#pragma unroll
    for (int mt = 0; mt < 4; mt++)
#pragma unroll
        for (int nt = 0; nt < 4; nt++)
#pragma unroll
            for (int r = 0; r < 4; r++) acc[mt][nt][r] = 0.f;

    // global staging addresses
    int aO = tid >> 1;                    // 0..127  (output channel)
    int aK = (tid & 1) * 8;               // 0 or 8
    const float* aSrc = Wt + (size_t)aO * KDIM + aK;
    // permuted m index: pairs (g, g+8) adjacent
    int aPerm = ((aO >> 4) << 4) + ((aO & 7) << 1) + ((aO >> 3) & 1);

    int bR = tid >> 4;                    // 0..15 (k row)
    int bC = (tid & 15) * 8;              // 0..120
    const float* bSrc = g_col + ((size_t)bR << 14) + bn + bC;

    float4 ra0, ra1, rb0, rb1;
    ra0 = *(const float4*)aSrc;
    ra1 = *(const float4*)(aSrc + 4);
    rb0 = *(const float4*)bSrc;
    rb1 = *(const float4*)(bSrc + 4);

    const int NIT = KDIM / GBK;           // 72
    for (int it = 0; it < NIT; it++) {
        __syncthreads();
        // stage A (tf32-convert, scalar scatter into permuted layout)
        As[aK + 0][aPerm] = __uint_as_float(f2tf32(ra0.x));
        As[aK + 1][aPerm] = __uint_as_float(f2tf32(ra0.y));
        As[aK + 2][aPerm] = __uint_as_float(f2tf32(ra0.z));
        As[aK + 3][aPerm] = __uint_as_float(f2tf32(ra0.w));
        As[aK + 4][aPerm] = __uint_as_float(f2tf32(ra1.x));
        As[aK + 5][aPerm] = __uint_as_float(f2tf32(ra1.y));
        As[aK + 6][aPerm] = __uint_as_float(f2tf32(ra1.z));
        As[aK + 7][aPerm] = __uint_as_float(f2tf32(ra1.w));
        // stage B
        float4 tb0, tb1;
        tb0.x = __uint_as_float(f2tf32(rb0.x)); tb0.y = __uint_as_float(f2tf32(rb0.y));
        tb0.z = __uint_as_float(f2tf32(rb0.z)); tb0.w = __uint_as_float(f2tf32(rb0.w));
        tb1.x = __uint_as_float(f2tf32(rb1.x)); tb1.y = __uint_as_float(f2tf32(rb1.y));
        tb1.z = __uint_as_float(f2tf32(rb1.z)); tb1.w = __uint_as_float(f2tf32(rb1.w));
        *(float4*)&Bs[bR][bC] = tb0;
        *(float4*)&Bs[bR][bC + 4] = tb1;
        __syncthreads();

        if (it < NIT - 1) {
            aSrc += GBK;
            bSrc += (size_t)GBK << 14;
            ra0 = *(const float4*)aSrc;
            ra1 = *(const float4*)(aSrc + 4);
            rb0 = *(const float4*)bSrc;
            rb1 = *(const float4*)(bSrc + 4);
        }

#pragma unroll
        for (int ks = 0; ks < 2; ks++) {
            int k0 = ks * 8;
            uint32_t a[4][4], bb[4][2];
#pragma unroll
            for (int mt = 0; mt < 4; mt++) {
                int mbase = (wm * 4 + mt) * 16 + g * 2;
                float2 p0 = *(float2*)&As[k0 + q][mbase];
                float2 p1 = *(float2*)&As[k0 + q + 4][mbase];
                a[mt][0] = __float_as_uint(p0.x);
                a[mt][1] = __float_as_uint(p0.y);
                a[mt][2] = __float_as_uint(p1.x);
                a[mt][3] = __float_as_uint(p1.y);
            }
#pragma unroll
            for (int nt = 0; nt < 4; nt++) {
                int nbase = wn * 32 + nt * 8 + g;
                bb[nt][0] = __float_as_uint(Bs[k0 + q][nbase]);
                bb[nt][1] = __float_as_uint(Bs[k0 + q + 4][nbase]);
            }
#pragma unroll
            for (int mt = 0; mt < 4; mt++)
#pragma unroll
                for (int nt = 0; nt < 4; nt++) {
                    asm volatile(
                        "mma.sync.aligned.m16n8k8.row.col.f32.tf32.tf32.f32 "
                        "{%0,%1,%2,%3}, {%4,%5,%6,%7}, {%8,%9}, {%0,%1,%2,%3};"
                        : "+f"(acc[mt][nt][0]), "+f"(acc[mt][nt][1]),
                          "+f"(acc[mt][nt][2]), "+f"(acc[mt][nt][3])
                        : "r"(a[mt][0]), "r"(a[mt][1]), "r"(a[mt][2]), "r"(a[mt][3]),
                          "r"(bb[nt][0]), "r"(bb[nt][1]));
                }
        }
    }

    // epilogue: ng = bn + wn*32 + nt*8 + 2q (+1); m = wm*64 + mt*16 + g (+8)
#pragma unroll
    for (int mt = 0; mt < 4; mt++) {
#pragma unroll
        for (int nt = 0; nt < 4; nt++) {
            int ng = bn + wn * 32 + nt * 8 + 2 * q;
            int bidx = ng >> 12;
            int ij = ng & (HW - 1);
            int m0 = wm * 64 + mt * 16 + g;
            float2 v0 = make_float2(acc[mt][nt][0], acc[mt][nt][1]);
            float2 v1 = make_float2(acc[mt][nt][2], acc[mt][nt][3]);
            *(float2*)&out[(size_t)(((bidx << 7) + m0) << 12) + ij] = v0;
            *(float2*)&out[(size_t)(((bidx << 7) + m0 + 8) << 12) + ij] = v1;
        }
    }
}

// ---------------------------------------------------------------------------
extern "C" void kernel_launch(void* const* d_in, const int* in_sizes, int n_in,
                              void* d_out, int out_size) {
    const float* x      = (const float*)d_in[0];
    const float* offset = (const float*)d_in[1];
    const float* weight = (const float*)d_in[2];
    float* out = (float*)d_out;

    (void)in_sizes; (void)n_in; (void)out_size;

    meta_kernel<<<(B * NPTS * HW + 255) / 256, 256>>>(offset);

    dim3 g1(HW / 128, B, C / 32);
    im2col_kernel<<<g1, 128>>>(x);

    gemm_tc<<<NCOL / 128, 256>>>(weight, out);
}